// round 9
// baseline (speedup 1.0000x reference)
#include <cuda_runtime.h>

// Tree DP on deterministic 4-ary heap: L=4096, B=64, C=2.
// msg[b,cs,k] = lse_{cj}( E[b,cj,j] + msg[b,cj,j] + T[k,j,cs,cj] ), j=(k-1)>>2.
//
// Best-measured design (round 2: kernel 6.08us / wall 6.66us), rebanked.
// Grid (64 subtrees x 8 batch-groups) x 256 threads. Each block owns subtree
// root r in [21,85) and 8 batches; recomputes the 3-edge root->r path in
// registers (no cross-block dependency), then runs levels 3..5 with parent
// locals staged in smem. All T/E loads statically indexed and issued before
// the first barrier (single DRAM wave, max MLP).

#define LN  4096
#define BN  64
#define CLN 8192
#define BB  8            // batches per block
#define NG  (BN / BB)    // 8 batch groups

__device__ __forceinline__ float lse2(float a, float b) {
    float mx = fmaxf(a, b);
    float mn = fminf(a, b);
    return mx + __logf(1.0f + __expf(mn - mx));
}

__global__ void __launch_bounds__(256, 1)
k_all(const float* __restrict__ E, const float* __restrict__ T, float* __restrict__ M)
{
    __shared__ float sR[BB][2];          // local(r)  = E[r]+msg[r]
    __shared__ float s3[4][BB][2];       // locals of level-3 nodes
    __shared__ float s4[16][BB][2];      // locals of level-4 nodes

    const int tid = threadIdx.x;
    const int r   = 21 + blockIdx.x;     // subtree root, [21, 85)
    const int b0  = blockIdx.y * BB;

    const int p2 = (r - 1) >> 2;         // [5, 21)
    const int p1 = (p2 - 1) >> 2;        // [1, 5)

    // ================= prefetch: all statically-indexed loads =================
    // path (tid < 8): batch bb = tid
    float4 tA, tB, tC;
    float eR0, eR1, e10, e11, e20, e21, er0, er1;
    const bool doPath = (tid < BB);
    if (doPath) {
        int b = b0 + tid;
        tA = __ldg((const float4*)T + (p1 * LN + 0));
        tB = __ldg((const float4*)T + (p2 * LN + p1));
        tC = __ldg((const float4*)T + (r  * LN + p2));
        eR0 = E[b * CLN + 0];        eR1 = E[b * CLN + LN + 0];
        e10 = E[b * CLN + p1];       e11 = E[b * CLN + LN + p1];
        e20 = E[b * CLN + p2];       e21 = E[b * CLN + LN + p2];
        er0 = E[b * CLN + r];        er1 = E[b * CLN + LN + r];
    }
    // level 3 (tid < 32): child d = tid>>3, bb = tid&7
    float4 t3; float e30, e31; int k3 = 0;
    const bool doL3 = (tid < 4 * BB);
    if (doL3) {
        int d = tid >> 3;
        k3 = 4 * r + 1 + d;
        t3 = __ldg((const float4*)T + (k3 * LN + r));
        int b = b0 + (tid & (BB - 1));
        e30 = E[b * CLN + k3];  e31 = E[b * CLN + LN + k3];
    }
    // level 4 (tid < 128): node n = tid>>3, bb = tid&7
    float4 t4; float e40, e41; int k4 = 0, j4 = 0;
    const bool doL4 = (tid < 16 * BB);
    if (doL4) {
        int n = tid >> 3;
        k4 = 16 * r + 5 + n;
        j4 = (k4 - 1) >> 2;
        t4 = __ldg((const float4*)T + (k4 * LN + j4));
        int b = b0 + (tid & (BB - 1));
        e40 = E[b * CLN + k4];  e41 = E[b * CLN + LN + k4];
    }
    // level 5: two items per thread, i = tid + it*256; n = i>>3, bb = i&7
    float4 t5[2]; int k5[2], j5[2]; bool v5[2];
    #pragma unroll
    for (int it = 0; it < 2; ++it) {
        int i = tid + it * 256;
        int n = i >> 3;                          // 0..63
        k5[it] = 64 * r + 21 + n;
        v5[it] = (k5[it] < LN);
        j5[it] = (k5[it] - 1) >> 2;
        if (v5[it])
            t5[it] = __ldg((const float4*)T + (k5[it] * LN + j5[it]));
    }

    // node 0 never receives a message -> zero it (output poisoned).
    // One writer group only (blockIdx.x == 0).
    if (blockIdx.x == 0 && tid < 2 * BB) {
        int b = b0 + (tid >> 1), c = tid & 1;
        M[b * CLN + c * LN] = 0.0f;
    }

    // ================= path: root -> p1 -> p2 -> r (registers only) ==========
    if (doPath) {
        int b = b0 + tid;
        // msg[p1] (local of root = E[root]; msg[root] = 0)
        float m0 = lse2(eR0 + tA.x, eR1 + tA.y);
        float m1 = lse2(eR0 + tA.z, eR1 + tA.w);
        M[b * CLN + p1] = m0;  M[b * CLN + LN + p1] = m1;
        float l0 = e10 + m0, l1 = e11 + m1;
        // msg[p2]
        m0 = lse2(l0 + tB.x, l1 + tB.y);
        m1 = lse2(l0 + tB.z, l1 + tB.w);
        M[b * CLN + p2] = m0;  M[b * CLN + LN + p2] = m1;
        l0 = e20 + m0;  l1 = e21 + m1;
        // msg[r]
        m0 = lse2(l0 + tC.x, l1 + tC.y);
        m1 = lse2(l0 + tC.z, l1 + tC.w);
        M[b * CLN + r] = m0;   M[b * CLN + LN + r] = m1;
        sR[tid][0] = er0 + m0;
        sR[tid][1] = er1 + m1;
    }
    __syncthreads();

    // ================= level 3 ================================================
    if (doL3) {
        int bb = tid & (BB - 1);
        float l0 = sR[bb][0], l1 = sR[bb][1];
        float m0 = lse2(l0 + t3.x, l1 + t3.y);
        float m1 = lse2(l0 + t3.z, l1 + t3.w);
        int b = b0 + bb;
        M[b * CLN + k3] = m0;  M[b * CLN + LN + k3] = m1;
        int d = tid >> 3;
        s3[d][bb][0] = e30 + m0;
        s3[d][bb][1] = e31 + m1;
    }
    __syncthreads();

    // ================= level 4 ================================================
    if (doL4) {
        int bb = tid & (BB - 1);
        int pd = j4 - (4 * r + 1);               // parent's level-3 slot, 0..3
        float l0 = s3[pd][bb][0], l1 = s3[pd][bb][1];
        float m0 = lse2(l0 + t4.x, l1 + t4.y);
        float m1 = lse2(l0 + t4.z, l1 + t4.w);
        int b = b0 + bb;
        M[b * CLN + k4] = m0;  M[b * CLN + LN + k4] = m1;
        int n = tid >> 3;
        s4[n][bb][0] = e40 + m0;
        s4[n][bb][1] = e41 + m1;
    }
    __syncthreads();

    // ================= level 5 (leaves, straight to global) ==================
    #pragma unroll
    for (int it = 0; it < 2; ++it) {
        if (v5[it]) {
            int i  = tid + it * 256;
            int bb = i & (BB - 1);
            int pn = j5[it] - (16 * r + 5);      // parent's level-4 slot, 0..15
            float l0 = s4[pn][bb][0], l1 = s4[pn][bb][1];
            float m0 = lse2(l0 + t5[it].x, l1 + t5[it].y);
            float m1 = lse2(l0 + t5[it].z, l1 + t5[it].w);
            int b = b0 + bb;
            M[b * CLN + k5[it]]      = m0;
            M[b * CLN + LN + k5[it]] = m1;
        }
    }
}

extern "C" void kernel_launch(void* const* d_in, const int* in_sizes, int n_in,
                              void* d_out, int out_size) {
    const float* E = (const float*)d_in[0];   // emissions   [B, C, L] f32
    const float* T = (const float*)d_in[1];   // transitions [L, L, C, C] f32
    float* M = (float*)d_out;                 // messages    [B, C, L] f32

    dim3 grid(64, NG);                        // 64 subtrees x 8 batch groups
    k_all<<<grid, 256>>>(E, T, M);
}

// round 10
// speedup vs baseline: 1.0332x; 1.0332x over previous
#include <cuda_runtime.h>

// Tree DP on deterministic 4-ary heap: L=4096, B=64, C=2.
// msg[b,cs,k] = lse_{cj}( E[b,cj,j] + msg[b,cj,j] + T[k,j,cs,cj] ), j=(k-1)>>2.
//
// Warp-autonomous (zero barriers, zero smem): each WARP owns (subtree r in
// [21,85), batch b). All lanes redundantly compute the 3-edge root->r path
// (broadcast loads); levels 3-5 propagate parent locals via shfl. All loads
// are statically indexed and issued up front (one DRAM wave, max MLP).
// Within-era fastest variant (R6: 6.56us) + node-0 single-writer + predicated
// dead E loads.

#define LN  4096
#define CLN 8192

__device__ __forceinline__ float lse2(float a, float b) {
    float mx = fmaxf(a, b);
    float mn = fminf(a, b);
    return mx + __logf(1.0f + __expf(mn - mx));
}

__global__ void __launch_bounds__(256, 1)
k_all(const float* __restrict__ E, const float* __restrict__ T, float* __restrict__ M)
{
    const int lane = threadIdx.x & 31;
    const int w    = threadIdx.x >> 5;
    const int r    = 21 + blockIdx.x;            // subtree root, [21,85)
    const int b    = blockIdx.y * 8 + w;         // this warp's batch

    const int p2 = (r - 1) >> 2;
    const int p1 = (p2 - 1) >> 2;

    const float4* __restrict__ T4 = (const float4*)T;
    const float*  __restrict__ Eb = E + b * CLN;

    // ---------------- prefetch everything (static indices, max MLP) ---------
    float4 tA = __ldg(T4 + p1 * LN + 0);
    float4 tB = __ldg(T4 + p2 * LN + p1);
    float4 tC = __ldg(T4 + r  * LN + p2);
    float eR0 = Eb[0],  eR1 = Eb[LN];
    float e10 = Eb[p1], e11 = Eb[LN + p1];
    float e20 = Eb[p2], e21 = Eb[LN + p2];
    float er0 = Eb[r],  er1 = Eb[LN + r];

    // level 3: node n3 = lane&3 (shfl sources are lanes 0-3 only)
    const int n3 = lane & 3;
    const int k3 = 4 * r + 1 + n3;
    float4 t3 = __ldg(T4 + k3 * LN + r);
    float e30 = 0.f, e31 = 0.f;
    if (lane < 4) { e30 = Eb[k3];  e31 = Eb[LN + k3]; }

    // level 4: node n4 = lane&15 (shfl sources are lanes 0-15 only)
    const int n4 = lane & 15;
    const int k4 = 16 * r + 5 + n4;
    float4 t4 = __ldg(T4 + k4 * LN + ((k4 - 1) >> 2));
    float e40 = 0.f, e41 = 0.f;
    if (lane < 16) { e40 = Eb[k4];  e41 = Eb[LN + k4]; }

    // level 5 (leaves, no E needed): nodes lane and lane+32
    const int k5a = 64 * r + 21 + lane;
    const int k5b = k5a + 32;
    const bool va = (k5a < LN), vb = (k5b < LN);
    float4 t5a, t5b;
    if (va) t5a = __ldg(T4 + k5a * LN + ((k5a - 1) >> 2));
    if (vb) t5b = __ldg(T4 + k5b * LN + ((k5b - 1) >> 2));

    // node 0 never receives a message -> zero it (output poisoned); one
    // writer group only.
    if (blockIdx.x == 0 && lane < 2)
        M[b * CLN + lane * LN] = 0.0f;

    // ---------------- path root -> p1 -> p2 -> r (all lanes, redundant) -----
    float m0 = lse2(eR0 + tA.x, eR1 + tA.y);
    float m1 = lse2(eR0 + tA.z, eR1 + tA.w);
    if (lane == 0) { M[b * CLN + p1] = m0;  M[b * CLN + LN + p1] = m1; }
    float l0 = e10 + m0, l1 = e11 + m1;

    m0 = lse2(l0 + tB.x, l1 + tB.y);
    m1 = lse2(l0 + tB.z, l1 + tB.w);
    if (lane == 0) { M[b * CLN + p2] = m0;  M[b * CLN + LN + p2] = m1; }
    l0 = e20 + m0;  l1 = e21 + m1;

    m0 = lse2(l0 + tC.x, l1 + tC.y);
    m1 = lse2(l0 + tC.z, l1 + tC.w);
    if (lane == 0) { M[b * CLN + r] = m0;   M[b * CLN + LN + r] = m1; }
    const float lr0 = er0 + m0, lr1 = er1 + m1;     // local(r), in every lane

    // ---------------- level 3 (4 nodes; lane holds node lane&3) -------------
    float m30 = lse2(lr0 + t3.x, lr1 + t3.y);
    float m31 = lse2(lr0 + t3.z, lr1 + t3.w);
    if (lane < 4) { M[b * CLN + k3] = m30;  M[b * CLN + LN + k3] = m31; }
    float l30 = e30 + m30, l31 = e31 + m31;

    // ---------------- level 4 (16 nodes; lane holds node lane&15) -----------
    float p40 = __shfl_sync(0xffffffffu, l30, n4 >> 2);
    float p41 = __shfl_sync(0xffffffffu, l31, n4 >> 2);
    float m40 = lse2(p40 + t4.x, p41 + t4.y);
    float m41 = lse2(p40 + t4.z, p41 + t4.w);
    if (lane < 16) { M[b * CLN + k4] = m40;  M[b * CLN + LN + k4] = m41; }
    float l40 = e40 + m40, l41 = e41 + m41;

    // ---------------- level 5 (up to 64 leaves) ------------------------------
    float a0 = __shfl_sync(0xffffffffu, l40, lane >> 2);          // parents 0..7
    float a1 = __shfl_sync(0xffffffffu, l41, lane >> 2);
    float c0 = __shfl_sync(0xffffffffu, l40, 8 + (lane >> 2));    // parents 8..15
    float c1 = __shfl_sync(0xffffffffu, l41, 8 + (lane >> 2));
    if (va) {
        float x0 = lse2(a0 + t5a.x, a1 + t5a.y);
        float x1 = lse2(a0 + t5a.z, a1 + t5a.w);
        M[b * CLN + k5a] = x0;  M[b * CLN + LN + k5a] = x1;       // coalesced
    }
    if (vb) {
        float y0 = lse2(c0 + t5b.x, c1 + t5b.y);
        float y1 = lse2(c0 + t5b.z, c1 + t5b.w);
        M[b * CLN + k5b] = y0;  M[b * CLN + LN + k5b] = y1;
    }
}

extern "C" void kernel_launch(void* const* d_in, const int* in_sizes, int n_in,
                              void* d_out, int out_size) {
    const float* E = (const float*)d_in[0];   // emissions   [B, C, L] f32
    const float* T = (const float*)d_in[1];   // transitions [L, L, C, C] f32
    float* M = (float*)d_out;                 // messages    [B, C, L] f32

    dim3 grid(64, 8);                         // 64 subtrees x 8 batch-groups
    k_all<<<grid, 256>>>(E, T, M);
}

// round 11
// speedup vs baseline: 1.3462x; 1.3029x over previous
#include <cuda_runtime.h>

// Tree DP on deterministic 4-ary heap: L=4096, B=64, C=2.
// msg[b,cs,k] = lse_{cj}( E[b,cj,j] + msg[b,cj,j] + T[k,j,cs,cj] ), j=(k-1)>>2.
//
// Warp-autonomous, zero barriers / zero smem. Each WARP owns (subtree r in
// [21,85), TWO batches bA,bB): T lines + index math amortized over 2 batches
// (2048 warps, ~25% fewer issued instructions than 1-batch/warp) and the two
// batches' lse2 chains interleave for ILP across the serial MUFU exp->log.
// Parent locals propagate via shfl. All loads issued up front (one DRAM wave).

#define LN  4096
#define CLN 8192

__device__ __forceinline__ float lse2(float a, float b) {
    float mx = fmaxf(a, b);
    float mn = fminf(a, b);
    return mx + __logf(1.0f + __expf(mn - mx));
}

__global__ void __launch_bounds__(256, 1)
k_all(const float* __restrict__ E, const float* __restrict__ T, float* __restrict__ M)
{
    const int lane = threadIdx.x & 31;
    const int w    = threadIdx.x >> 5;
    const int r    = 21 + blockIdx.x;               // subtree root, [21,85)
    const int bA   = (blockIdx.y * 8 + w) * 2;      // batches bA, bA+1
    const int bB   = bA + 1;

    const int p2 = (r - 1) >> 2;
    const int p1 = (p2 - 1) >> 2;

    const float4* __restrict__ T4 = (const float4*)T;
    const float*  __restrict__ EA = E + bA * CLN;
    const float*  __restrict__ EB = E + bB * CLN;
    float* __restrict__ MA = M + bA * CLN;
    float* __restrict__ MB = M + bB * CLN;

    // ---------------- prefetch (static indices, one DRAM wave) --------------
    float4 tA = __ldg(T4 + p1 * LN + 0);
    float4 tB = __ldg(T4 + p2 * LN + p1);
    float4 tC = __ldg(T4 + r  * LN + p2);

    float aR0 = EA[0],  aR1 = EA[LN],      bR0 = EB[0],  bR1 = EB[LN];
    float a10 = EA[p1], a11 = EA[LN + p1], b10 = EB[p1], b11 = EB[LN + p1];
    float a20 = EA[p2], a21 = EA[LN + p2], b20 = EB[p2], b21 = EB[LN + p2];
    float ar0 = EA[r],  ar1 = EA[LN + r],  br0 = EB[r],  br1 = EB[LN + r];

    // level 3: node n3 = lane&3 (shfl sources: lanes 0-3)
    const int n3 = lane & 3;
    const int k3 = 4 * r + 1 + n3;
    float4 t3 = __ldg(T4 + k3 * LN + r);
    float a30 = 0.f, a31 = 0.f, b30 = 0.f, b31 = 0.f;
    if (lane < 4) {
        a30 = EA[k3];  a31 = EA[LN + k3];
        b30 = EB[k3];  b31 = EB[LN + k3];
    }

    // level 4: node n4 = lane&15 (shfl sources: lanes 0-15)
    const int n4 = lane & 15;
    const int k4 = 16 * r + 5 + n4;
    float4 t4 = __ldg(T4 + k4 * LN + ((k4 - 1) >> 2));
    float a40 = 0.f, a41 = 0.f, b40 = 0.f, b41 = 0.f;
    if (lane < 16) {
        a40 = EA[k4];  a41 = EA[LN + k4];
        b40 = EB[k4];  b41 = EB[LN + k4];
    }

    // level 5 (leaves, no E needed): nodes lane and lane+32
    const int k5a = 64 * r + 21 + lane;
    const int k5b = k5a + 32;
    const bool va = (k5a < LN), vb = (k5b < LN);
    float4 t5a, t5b;
    if (va) t5a = __ldg(T4 + k5a * LN + ((k5a - 1) >> 2));
    if (vb) t5b = __ldg(T4 + k5b * LN + ((k5b - 1) >> 2));

    // node 0 never receives a message -> zero (output poisoned); single writer group
    if (blockIdx.x == 0 && lane < 2) {
        MA[lane * LN] = 0.0f;
        MB[lane * LN] = 0.0f;
    }

    // ---------------- path root -> p1 -> p2 -> r (all lanes; 2 batches) -----
    float ma0 = lse2(aR0 + tA.x, aR1 + tA.y);
    float mb0 = lse2(bR0 + tA.x, bR1 + tA.y);
    float ma1 = lse2(aR0 + tA.z, aR1 + tA.w);
    float mb1 = lse2(bR0 + tA.z, bR1 + tA.w);
    if (lane == 0) {
        MA[p1] = ma0;  MA[LN + p1] = ma1;
        MB[p1] = mb0;  MB[LN + p1] = mb1;
    }
    float la0 = a10 + ma0, la1 = a11 + ma1;
    float lb0 = b10 + mb0, lb1 = b11 + mb1;

    ma0 = lse2(la0 + tB.x, la1 + tB.y);
    mb0 = lse2(lb0 + tB.x, lb1 + tB.y);
    ma1 = lse2(la0 + tB.z, la1 + tB.w);
    mb1 = lse2(lb0 + tB.z, lb1 + tB.w);
    if (lane == 0) {
        MA[p2] = ma0;  MA[LN + p2] = ma1;
        MB[p2] = mb0;  MB[LN + p2] = mb1;
    }
    la0 = a20 + ma0;  la1 = a21 + ma1;
    lb0 = b20 + mb0;  lb1 = b21 + mb1;

    ma0 = lse2(la0 + tC.x, la1 + tC.y);
    mb0 = lse2(lb0 + tC.x, lb1 + tC.y);
    ma1 = lse2(la0 + tC.z, la1 + tC.w);
    mb1 = lse2(lb0 + tC.z, lb1 + tC.w);
    if (lane == 0) {
        MA[r] = ma0;   MA[LN + r] = ma1;
        MB[r] = mb0;   MB[LN + r] = mb1;
    }
    const float lrA0 = ar0 + ma0, lrA1 = ar1 + ma1;
    const float lrB0 = br0 + mb0, lrB1 = br1 + mb1;

    // ---------------- level 3 (4 nodes; lane holds node lane&3) -------------
    float mA30 = lse2(lrA0 + t3.x, lrA1 + t3.y);
    float mB30 = lse2(lrB0 + t3.x, lrB1 + t3.y);
    float mA31 = lse2(lrA0 + t3.z, lrA1 + t3.w);
    float mB31 = lse2(lrB0 + t3.z, lrB1 + t3.w);
    if (lane < 4) {
        MA[k3] = mA30;  MA[LN + k3] = mA31;
        MB[k3] = mB30;  MB[LN + k3] = mB31;
    }
    float lA30 = a30 + mA30, lA31 = a31 + mA31;
    float lB30 = b30 + mB30, lB31 = b31 + mB31;

    // ---------------- level 4 (16 nodes; lane holds node lane&15) -----------
    const int s4 = n4 >> 2;
    float pA0 = __shfl_sync(0xffffffffu, lA30, s4);
    float pA1 = __shfl_sync(0xffffffffu, lA31, s4);
    float pB0 = __shfl_sync(0xffffffffu, lB30, s4);
    float pB1 = __shfl_sync(0xffffffffu, lB31, s4);
    float mA40 = lse2(pA0 + t4.x, pA1 + t4.y);
    float mB40 = lse2(pB0 + t4.x, pB1 + t4.y);
    float mA41 = lse2(pA0 + t4.z, pA1 + t4.w);
    float mB41 = lse2(pB0 + t4.z, pB1 + t4.w);
    if (lane < 16) {
        MA[k4] = mA40;  MA[LN + k4] = mA41;
        MB[k4] = mB40;  MB[LN + k4] = mB41;
    }
    float lA40 = a40 + mA40, lA41 = a41 + mA41;
    float lB40 = b40 + mB40, lB41 = b41 + mB41;

    // ---------------- level 5 (up to 64 leaves) ------------------------------
    const int s5a = lane >> 2;
    const int s5b = 8 + (lane >> 2);
    float xA0 = __shfl_sync(0xffffffffu, lA40, s5a);
    float xA1 = __shfl_sync(0xffffffffu, lA41, s5a);
    float xB0 = __shfl_sync(0xffffffffu, lB40, s5a);
    float xB1 = __shfl_sync(0xffffffffu, lB41, s5a);
    float yA0 = __shfl_sync(0xffffffffu, lA40, s5b);
    float yA1 = __shfl_sync(0xffffffffu, lA41, s5b);
    float yB0 = __shfl_sync(0xffffffffu, lB40, s5b);
    float yB1 = __shfl_sync(0xffffffffu, lB41, s5b);
    if (va) {
        float u0 = lse2(xA0 + t5a.x, xA1 + t5a.y);
        float v0 = lse2(xB0 + t5a.x, xB1 + t5a.y);
        float u1 = lse2(xA0 + t5a.z, xA1 + t5a.w);
        float v1 = lse2(xB0 + t5a.z, xB1 + t5a.w);
        MA[k5a] = u0;  MA[LN + k5a] = u1;       // coalesced
        MB[k5a] = v0;  MB[LN + k5a] = v1;
    }
    if (vb) {
        float u0 = lse2(yA0 + t5b.x, yA1 + t5b.y);
        float v0 = lse2(yB0 + t5b.x, yB1 + t5b.y);
        float u1 = lse2(yA0 + t5b.z, yA1 + t5b.w);
        float v1 = lse2(yB0 + t5b.z, yB1 + t5b.w);
        MA[k5b] = u0;  MA[LN + k5b] = u1;
        MB[k5b] = v0;  MB[LN + k5b] = v1;
    }
}

extern "C" void kernel_launch(void* const* d_in, const int* in_sizes, int n_in,
                              void* d_out, int out_size) {
    const float* E = (const float*)d_in[0];   // emissions   [B, C, L] f32
    const float* T = (const float*)d_in[1];   // transitions [L, L, C, C] f32
    float* M = (float*)d_out;                 // messages    [B, C, L] f32

    dim3 grid(64, 4);                         // 64 subtrees x 4 groups of 2x8 batches
    k_all<<<grid, 256>>>(E, T, M);
}